// round 2
// baseline (speedup 1.0000x reference)
#include <cuda_runtime.h>
#include <math.h>

#define Bb 4
#define SQ 1024
#define SKV 2048
#define DM 1024
#define NH 16
#define DH 64

// Scratch (device globals; no runtime allocation allowed)
__device__ float g_Q[Bb*NH*SQ*DH];     //  16.8 MB  [B,H,Sq,Dh]
__device__ float g_K[Bb*NH*SKV*DH];    //  33.6 MB  [B,H,Skv,Dh]
__device__ float g_V[Bb*NH*SKV*DH];    //  33.6 MB  [B,H,Skv,Dh]
__device__ float g_ctx[Bb*SQ*DM];      //  16.8 MB  [B,Sq,H*Dh]
__device__ float g_proj[Bb*SQ*DM];     //  16.8 MB  [B,Sq,DM]
__device__ float g_rc[SKV*32];         // rope cos table [s][pair]
__device__ float g_rs[SKV*32];         // rope sin table [s][pair]

// ---------------------------------------------------------------------------
// RoPE table in double precision (immune to --use_fast_math).
// ---------------------------------------------------------------------------
__global__ void rope_table_k() {
    int idx = blockIdx.x * blockDim.x + threadIdx.x;   // 0 .. SKV*32-1
    if (idx >= SKV * 32) return;
    int s = idx >> 5;
    int p = idx & 31;
    double inv = pow(10000.0, -(double)(2 * p) / 64.0);
    double ang = (double)s * inv;
    g_rc[idx] = (float)cos(ang);
    g_rs[idx] = (float)sin(ang);
}

// ---------------------------------------------------------------------------
// Tiled SGEMM  C[M,1024] = A[M,1024] @ W[1024,1024]
// MODE 0: V  -> write [B,H,S,Dh]
// MODE 1: Q  -> rope + 0.125 scale -> [B,H,S,Dh]
// MODE 2: K  -> rope               -> [B,H,S,Dh]
// MODE 3: ctx @ Wo -> plain row-major g_proj
// ---------------------------------------------------------------------------
template<int MODE>
__global__ __launch_bounds__(256)
void gemm_k(const float* __restrict__ A, const float* __restrict__ W, int S) {
    __shared__ float As[16][132];   // [k][m], padded
    __shared__ float Bs[16][128];   // [k][n]

    const float* Ain = (MODE == 3) ? g_ctx : A;
    float* out = (MODE == 0) ? g_V : (MODE == 1) ? g_Q : (MODE == 2) ? g_K : g_proj;

    int tid = threadIdx.x;
    int bx = blockIdx.x, by = blockIdx.y;
    int tx = tid & 15, ty = tid >> 4;
    const int arow0 = by * 128, bcol0 = bx * 128;

    float acc[8][8];
    #pragma unroll
    for (int i = 0; i < 8; i++)
        #pragma unroll
        for (int j = 0; j < 8; j++) acc[i][j] = 0.f;

    for (int kt = 0; kt < DM; kt += 16) {
        #pragma unroll
        for (int li = 0; li < 2; li++) {
            int idx = tid + 256 * li;
            int r  = idx >> 2, c4 = (idx & 3) << 2;
            float4 va = *(const float4*)&Ain[(arow0 + r) * DM + kt + c4];
            As[c4 + 0][r] = va.x; As[c4 + 1][r] = va.y;
            As[c4 + 2][r] = va.z; As[c4 + 3][r] = va.w;
            int rb = idx >> 5, cb = (idx & 31) << 2;
            *(float4*)&Bs[rb][cb] = *(const float4*)&W[(kt + rb) * DM + bcol0 + cb];
        }
        __syncthreads();
        #pragma unroll
        for (int k = 0; k < 16; k++) {
            float a[8], b[8];
            *(float4*)(a)     = *(float4*)&As[k][ty * 8];
            *(float4*)(a + 4) = *(float4*)&As[k][ty * 8 + 4];
            *(float4*)(b)     = *(float4*)&Bs[k][tx * 8];
            *(float4*)(b + 4) = *(float4*)&Bs[k][tx * 8 + 4];
            #pragma unroll
            for (int i = 0; i < 8; i++)
                #pragma unroll
                for (int j = 0; j < 8; j++)
                    acc[i][j] = fmaf(a[i], b[j], acc[i][j]);
        }
        __syncthreads();
    }

    int m0 = arow0 + ty * 8;
    int n0 = bcol0 + tx * 8;
    if (MODE == 3) {
        #pragma unroll
        for (int i = 0; i < 8; i++)
            #pragma unroll
            for (int j = 0; j < 8; j++)
                out[(m0 + i) * DM + n0 + j] = acc[i][j];
    } else {
        #pragma unroll
        for (int i = 0; i < 8; i++) {
            int m = m0 + i;
            int b = m / S;
            int s = m - b * S;
            #pragma unroll
            for (int p = 0; p < 4; p++) {
                int n  = n0 + 2 * p;
                int h  = n >> 6;
                int dd = n & 63;            // even
                float o1 = acc[i][2 * p], o2 = acc[i][2 * p + 1];
                if (MODE == 1 || MODE == 2) {
                    int ti = s * 32 + (dd >> 1);
                    float c  = g_rc[ti];
                    float sn = g_rs[ti];
                    float r1 = o1 * c - o2 * sn;
                    float r2 = o2 * c + o1 * sn;
                    if (MODE == 1) { r1 *= 0.125f; r2 *= 0.125f; }  // 1/sqrt(64)
                    o1 = r1; o2 = r2;
                }
                int idx = ((b * NH + h) * S + s) * DH + dd;
                out[idx]     = o1;
                out[idx + 1] = o2;
            }
        }
    }
}

// ---------------------------------------------------------------------------
// Flash attention. Grid (Sq/64, B*H), block 256.
// Q tile 64 rows; KV chunks of 32; online softmax; O in registers.
// Mask read as 32-bit words (bool promoted to int32/float32 by harness);
// nonzero bit pattern == valid key (covers both 1 and 1.0f).
// ---------------------------------------------------------------------------
__global__ __launch_bounds__(256)
void flash_k(const unsigned int* __restrict__ mask) {
    __shared__ float Qs[64][65];
    __shared__ float Ks[32][65];
    __shared__ float Vs[32][65];
    __shared__ float Ps[64][33];
    __shared__ float m_s[64], l_s[64], al_s[64];
    __shared__ unsigned int mk[32];

    int tid = threadIdx.x;
    int tx = tid & 15, ty = tid >> 4;
    int q0 = blockIdx.x * 64;
    int bh = blockIdx.y;
    int b  = bh >> 4;
    int h  = bh & 15;

    const float* Qg = g_Q + (bh * SQ + q0) * DH;
    const float* Kg = g_K + (size_t)bh * SKV * DH;
    const float* Vg = g_V + (size_t)bh * SKV * DH;

    for (int e = tid; e < 64 * 64; e += 256) Qs[e >> 6][e & 63] = Qg[e];
    if (tid < 64) { m_s[tid] = -INFINITY; l_s[tid] = 0.f; }

    float O[4][4];
    #pragma unroll
    for (int i = 0; i < 4; i++)
        #pragma unroll
        for (int j = 0; j < 4; j++) O[i][j] = 0.f;

    __syncthreads();

    for (int kc = 0; kc < SKV; kc += 32) {
        for (int e = tid; e < 32 * 64; e += 256) {
            Ks[e >> 6][e & 63] = Kg[kc * 64 + e];
            Vs[e >> 6][e & 63] = Vg[kc * 64 + e];
        }
        if (tid < 32) mk[tid] = mask[b * SKV + kc + tid];
        __syncthreads();

        // S = Q @ K^T  (64x32), this thread: rows ty*4+i, cols tx*2+j
        float sv[4][2];
        #pragma unroll
        for (int i = 0; i < 4; i++) { sv[i][0] = 0.f; sv[i][1] = 0.f; }
        #pragma unroll 8
        for (int d = 0; d < 64; d++) {
            float k0 = Ks[tx * 2 + 0][d];
            float k1 = Ks[tx * 2 + 1][d];
            #pragma unroll
            for (int i = 0; i < 4; i++) {
                float q = Qs[ty * 4 + i][d];
                sv[i][0] = fmaf(q, k0, sv[i][0]);
                sv[i][1] = fmaf(q, k1, sv[i][1]);
            }
        }
        bool ok0 = mk[tx * 2 + 0] != 0u;
        bool ok1 = mk[tx * 2 + 1] != 0u;
        #pragma unroll
        for (int i = 0; i < 4; i++) {
            Ps[ty * 4 + i][tx * 2 + 0] = ok0 ? sv[i][0] : -1000000000.0f;
            Ps[ty * 4 + i][tx * 2 + 1] = ok1 ? sv[i][1] : -1000000000.0f;
        }
        __syncthreads();

        // online softmax per row (64 rows on 64 threads)
        if (tid < 64) {
            int r = tid;
            float mold = m_s[r], mx = mold;
            #pragma unroll 8
            for (int c = 0; c < 32; c++) mx = fmaxf(mx, Ps[r][c]);
            float al = expf(mold - mx);
            float sum = 0.f;
            #pragma unroll 8
            for (int c = 0; c < 32; c++) {
                float p = expf(Ps[r][c] - mx);
                Ps[r][c] = p;
                sum += p;
            }
            m_s[r]  = mx;
            al_s[r] = al;
            l_s[r]  = l_s[r] * al + sum;
        }
        __syncthreads();

        // rescale O, accumulate P @ V  (O rows ty*4+i, cols tx*4+j)
        #pragma unroll
        for (int i = 0; i < 4; i++) {
            float al = al_s[ty * 4 + i];
            #pragma unroll
            for (int j = 0; j < 4; j++) O[i][j] *= al;
        }
        #pragma unroll 8
        for (int k = 0; k < 32; k++) {
            float v[4];
            #pragma unroll
            for (int j = 0; j < 4; j++) v[j] = Vs[k][tx * 4 + j];
            #pragma unroll
            for (int i = 0; i < 4; i++) {
                float p = Ps[ty * 4 + i][k];
                #pragma unroll
                for (int j = 0; j < 4; j++) O[i][j] = fmaf(p, v[j], O[i][j]);
            }
        }
        __syncthreads();
    }

    #pragma unroll
    for (int i = 0; i < 4; i++) {
        int r = ty * 4 + i;
        float invl = 1.0f / l_s[r];
        #pragma unroll
        for (int j = 0; j < 4; j++)
            g_ctx[(b * SQ + q0 + r) * DM + h * 64 + tx * 4 + j] = O[i][j] * invl;
    }
}

// ---------------------------------------------------------------------------
// Residual + LayerNorm, one block per row.
// ---------------------------------------------------------------------------
__global__ __launch_bounds__(256)
void ln_k(const float* __restrict__ dq, const float* __restrict__ gamma,
          const float* __restrict__ beta, float* __restrict__ out) {
    int row = blockIdx.x;
    int tid = threadIdx.x;
    __shared__ float red[256];
    __shared__ float mu_s, var_s;

    float x[4];
    float s = 0.f;
    #pragma unroll
    for (int u = 0; u < 4; u++) {
        int idx = u * 256 + tid;
        x[u] = dq[row * DM + idx] + g_proj[row * DM + idx];
        s += x[u];
    }
    red[tid] = s;
    __syncthreads();
    for (int st = 128; st > 0; st >>= 1) {
        if (tid < st) red[tid] += red[tid + st];
        __syncthreads();
    }
    if (tid == 0) mu_s = red[0] * (1.0f / DM);
    __syncthreads();
    float mu = mu_s;

    s = 0.f;
    #pragma unroll
    for (int u = 0; u < 4; u++) {
        float d2 = x[u] - mu;
        s += d2 * d2;
    }
    red[tid] = s;
    __syncthreads();
    for (int st = 128; st > 0; st >>= 1) {
        if (tid < st) red[tid] += red[tid + st];
        __syncthreads();
    }
    if (tid == 0) var_s = red[0] * (1.0f / DM);
    __syncthreads();
    float rstd = rsqrtf(var_s + 0.001f);

    #pragma unroll
    for (int u = 0; u < 4; u++) {
        int idx = u * 256 + tid;
        out[row * DM + idx] = (x[u] - mu) * rstd * gamma[idx] + beta[idx];
    }
}

// ---------------------------------------------------------------------------
extern "C" void kernel_launch(void* const* d_in, const int* in_sizes, int n_in,
                              void* d_out, int out_size) {
    const float* dq    = (const float*)d_in[0];
    const float* ekv   = (const float*)d_in[1];
    const unsigned int* mask = (const unsigned int*)d_in[2];
    const float* Wq    = (const float*)d_in[3];
    const float* Wk    = (const float*)d_in[4];
    const float* Wv    = (const float*)d_in[5];
    const float* Wo    = (const float*)d_in[6];
    const float* gamma = (const float*)d_in[7];
    const float* beta  = (const float*)d_in[8];
    float* out = (float*)d_out;

    // RoPE cos/sin table (double precision, fast-math immune)
    rope_table_k<<<(SKV * 32 + 255) / 256, 256>>>();

    // Projections + RoPE (Q scaled by 1/sqrt(Dh))
    gemm_k<1><<<dim3(8, 32), 256>>>(dq,  Wq, SQ);
    gemm_k<2><<<dim3(8, 64), 256>>>(ekv, Wk, SKV);
    gemm_k<0><<<dim3(8, 64), 256>>>(ekv, Wv, SKV);

    // Attention
    flash_k<<<dim3(SQ / 64, Bb * NH), 256>>>(mask);

    // Output projection
    gemm_k<3><<<dim3(8, 32), 256>>>(nullptr, Wo, SQ);

    // Residual + LayerNorm
    ln_k<<<Bb * SQ, 256>>>(dq, gamma, beta, out);
}